// round 1
// baseline (speedup 1.0000x reference)
#include <cuda_runtime.h>
#include <cuda_bf16.h>
#include <cstdint>

// ---------------- problem constants ----------------
#define LSEQ    4096
#define DMODEL  1024
#define DINNER  2048
#define DCONV   4
#define DTRANK  64
#define DSTATE  16
#define DBLW    (DTRANK + 2*DSTATE)   // 96
#define CHUNK   128
#define NCHUNK  (LSEQ / CHUNK)        // 32
#define KSPLIT  8

// ---------------- scratch (static device globals; no runtime alloc) ----------------
__device__ float g_xr[(size_t)LSEQ * 2 * DINNER];          // 64 MB: [xi | res]
__device__ float g_xs[(size_t)LSEQ * DINNER];              // 32 MB
__device__ float g_dblpart[(size_t)KSPLIT * LSEQ * DBLW];  // 12.6 MB
__device__ float g_dbl[(size_t)LSEQ * DBLW];               // 1.5 MB
__device__ float g_delta[(size_t)LSEQ * DINNER];           // 32 MB
__device__ float g_yg[(size_t)LSEQ * DINNER];              // 32 MB
__device__ float g_prodA[(size_t)NCHUNK * DINNER * DSTATE];// 4 MB
__device__ float g_hend [(size_t)NCHUNK * DINNER * DSTATE];// 4 MB
__device__ float g_hinit[(size_t)NCHUNK * DINNER * DSTATE];// 4 MB

// ---------------- generic SGEMM: C = A(MxK,lda) * B(NxK,ldb)^T ----------------
// BM=BN=128, BK=8, 256 threads, 8x8 per thread, float4 smem paths.
// M must be a multiple of 128 here (always true: M=4096). N/K arbitrary-ish:
// N guarded (for N=96), K must be a multiple of 8 (1024/2048/64/2048: yes).
// Split-K: gridDim.z slices of kchunk, each writing to C + z*splitStride.
#define GBM 128
#define GBN 128
#define GBK 8

__global__ __launch_bounds__(256) void sgemm_nt(
    const float* __restrict__ A, int lda,
    const float* __restrict__ B, int ldb,
    float* __restrict__ C, int ldc,
    int M, int N, int K,
    int kchunk, size_t splitStride,
    const float* __restrict__ bias, int act)
{
    __shared__ float As[GBK][GBM];
    __shared__ float Bs[GBK][GBN];

    const int tid = threadIdx.x;
    const int rowBase = blockIdx.y * GBM;
    const int colBase = blockIdx.x * GBN;
    const int kbeg = blockIdx.z * kchunk;
    const int kend = kbeg + kchunk;
    C += (size_t)blockIdx.z * splitStride;

    const int lr = tid >> 1;          // 0..127
    const int lc = (tid & 1) * 4;     // 0 or 4

    const float* Aptr = A + (size_t)(rowBase + lr) * lda + lc;
    const float* Bptr = B + (size_t)(colBase + lr) * ldb + lc;
    const bool avalid = (rowBase + lr) < M;
    const bool bvalid = (colBase + lr) < N;

    const int tx = tid & 15;
    const int ty = tid >> 4;

    float acc[8][8];
#pragma unroll
    for (int i = 0; i < 8; ++i)
#pragma unroll
        for (int j = 0; j < 8; ++j) acc[i][j] = 0.f;

    for (int k0 = kbeg; k0 < kend; k0 += GBK) {
        float4 av = avalid ? *(const float4*)(Aptr + k0) : make_float4(0.f,0.f,0.f,0.f);
        float4 bv = bvalid ? *(const float4*)(Bptr + k0) : make_float4(0.f,0.f,0.f,0.f);
        __syncthreads();
        As[lc+0][lr] = av.x; As[lc+1][lr] = av.y; As[lc+2][lr] = av.z; As[lc+3][lr] = av.w;
        Bs[lc+0][lr] = bv.x; Bs[lc+1][lr] = bv.y; Bs[lc+2][lr] = bv.z; Bs[lc+3][lr] = bv.w;
        __syncthreads();
#pragma unroll
        for (int kk = 0; kk < GBK; ++kk) {
            float4 a0 = *(const float4*)&As[kk][ty*4];
            float4 a1 = *(const float4*)&As[kk][64 + ty*4];
            float4 b0 = *(const float4*)&Bs[kk][tx*4];
            float4 b1 = *(const float4*)&Bs[kk][64 + tx*4];
            float ra[8] = {a0.x,a0.y,a0.z,a0.w,a1.x,a1.y,a1.z,a1.w};
            float rb[8] = {b0.x,b0.y,b0.z,b0.w,b1.x,b1.y,b1.z,b1.w};
#pragma unroll
            for (int i = 0; i < 8; ++i)
#pragma unroll
                for (int j = 0; j < 8; ++j)
                    acc[i][j] = fmaf(ra[i], rb[j], acc[i][j]);
        }
    }

#pragma unroll
    for (int i = 0; i < 8; ++i) {
        int row = rowBase + ((i < 4) ? (ty*4 + i) : (64 + ty*4 + i - 4));
        if (row >= M) continue;
#pragma unroll
        for (int j = 0; j < 8; ++j) {
            int col = colBase + ((j < 4) ? (tx*4 + j) : (64 + tx*4 + j - 4));
            if (col >= N) continue;
            float v = acc[i][j];
            if (bias) v += bias[col];
            if (act == 1) v = (v > 20.f) ? v : log1pf(__expf(v));  // softplus
            C[(size_t)row * ldc + col] = v;
        }
    }
}

// ---------------- split-K reduce: g_dbl = sum_z g_dblpart[z] ----------------
__global__ void reduce_splitk(const float* __restrict__ part, float* __restrict__ out, int n)
{
    int i = blockIdx.x * blockDim.x + threadIdx.x;
    if (i >= n) return;
    float s = 0.f;
#pragma unroll
    for (int z = 0; z < KSPLIT; ++z) s += part[(size_t)z * n + i];
    out[i] = s;
}

// ---------------- causal depthwise conv(k=4) + bias + silu ----------------
__global__ void conv_silu(const float* __restrict__ xr,
                          const float* __restrict__ cw,
                          const float* __restrict__ cb,
                          float* __restrict__ xs)
{
    int idx = blockIdx.x * blockDim.x + threadIdx.x;
    if (idx >= LSEQ * DINNER) return;
    int t = idx / DINNER;
    int d = idx - t * DINNER;
    float acc = cb[d];
#pragma unroll
    for (int k = 0; k < DCONV; ++k) {
        int tt = t - (DCONV - 1) + k;
        if (tt >= 0) acc = fmaf(cw[d * DCONV + k], xr[(size_t)tt * (2*DINNER) + d], acc);
    }
    float sig = 1.f / (1.f + __expf(-acc));
    xs[idx] = acc * sig;
}

// ---------------- selective scan: 3-phase chunked ----------------
// Phase A: per (chunk, d, n) local scan with h0=0 -> hend, prodA.
__global__ __launch_bounds__(256) void scan_phaseA(
    const float* __restrict__ delta, const float* __restrict__ xs,
    const float* __restrict__ dbl, const float* __restrict__ A_log,
    float* __restrict__ prodA, float* __restrict__ hend)
{
    const int tid = threadIdx.x;
    const int n  = tid & 15;
    const int d  = blockIdx.x * 16 + (tid >> 4);
    const int chunk = blockIdx.y;
    const float Adn = -__expf(A_log[d * DSTATE + n]);
    const float* Bp = dbl + DTRANK;

    float h = 0.f, pA = 1.f;
    const int t0 = chunk * CHUNK;
#pragma unroll 4
    for (int t = t0; t < t0 + CHUNK; ++t) {
        float dl = delta[(size_t)t * DINNER + d];
        float xv = xs[(size_t)t * DINNER + d];
        float b  = Bp[(size_t)t * DBLW + n];
        float a  = __expf(dl * Adn);
        h  = fmaf(a, h, dl * xv * b);
        pA *= a;
    }
    int idx = chunk * (DINNER * DSTATE) + d * DSTATE + n;
    prodA[idx] = pA;
    hend[idx]  = h;
}

// Phase B: sequential over chunks (tiny): h-init for each chunk.
__global__ void scan_phaseB(const float* __restrict__ prodA,
                            const float* __restrict__ hend,
                            float* __restrict__ hinit)
{
    int i = blockIdx.x * blockDim.x + threadIdx.x;   // d*16+n
    if (i >= DINNER * DSTATE) return;
    float H = 0.f;
#pragma unroll
    for (int c = 0; c < NCHUNK; ++c) {
        int idx = c * (DINNER * DSTATE) + i;
        hinit[idx] = H;
        H = fmaf(prodA[idx], H, hend[idx]);
    }
}

// Phase C: re-scan each chunk with correct h0; fuse y = sum_n h*C + xs*D,
// then gate with silu(res) and write yg.
__global__ __launch_bounds__(256) void scan_phaseC(
    const float* __restrict__ delta, const float* __restrict__ xs,
    const float* __restrict__ dbl, const float* __restrict__ A_log,
    const float* __restrict__ Dv, const float* __restrict__ xr,
    const float* __restrict__ hinit, float* __restrict__ yg)
{
    const int tid = threadIdx.x;
    const int n  = tid & 15;
    const int d  = blockIdx.x * 16 + (tid >> 4);
    const int chunk = blockIdx.y;
    const float Adn = -__expf(A_log[d * DSTATE + n]);
    const float Dd  = Dv[d];
    const float* Bp = dbl + DTRANK;
    const float* Cp = dbl + DTRANK + DSTATE;

    float h = hinit[chunk * (DINNER * DSTATE) + d * DSTATE + n];
    const int t0 = chunk * CHUNK;
#pragma unroll 2
    for (int t = t0; t < t0 + CHUNK; ++t) {
        float dl = delta[(size_t)t * DINNER + d];
        float xv = xs[(size_t)t * DINNER + d];
        float b  = Bp[(size_t)t * DBLW + n];
        float c  = Cp[(size_t)t * DBLW + n];
        float a  = __expf(dl * Adn);
        h = fmaf(a, h, dl * xv * b);
        float p = h * c;
        p += __shfl_xor_sync(0xffffffffu, p, 1, 16);
        p += __shfl_xor_sync(0xffffffffu, p, 2, 16);
        p += __shfl_xor_sync(0xffffffffu, p, 4, 16);
        p += __shfl_xor_sync(0xffffffffu, p, 8, 16);
        if (n == 0) {
            float r   = xr[(size_t)t * (2*DINNER) + DINNER + d];
            float yv  = p + xv * Dd;
            float sig = 1.f / (1.f + __expf(-r));
            yg[(size_t)t * DINNER + d] = yv * (r * sig);
        }
    }
}

// ---------------- launcher ----------------
extern "C" void kernel_launch(void* const* d_in, const int* in_sizes, int n_in,
                              void* d_out, int out_size)
{
    const float* x      = (const float*)d_in[0];
    const float* W_in   = (const float*)d_in[1];
    const float* conv_w = (const float*)d_in[2];
    const float* conv_b = (const float*)d_in[3];
    const float* W_x    = (const float*)d_in[4];
    const float* W_dt   = (const float*)d_in[5];
    const float* b_dt   = (const float*)d_in[6];
    const float* A_log  = (const float*)d_in[7];
    const float* Dv     = (const float*)d_in[8];
    const float* W_out  = (const float*)d_in[9];
    float* out = (float*)d_out;

    float *xr, *xs, *dblp, *dbl, *delta, *yg, *pA, *he, *hi;
    cudaGetSymbolAddress((void**)&xr,   g_xr);
    cudaGetSymbolAddress((void**)&xs,   g_xs);
    cudaGetSymbolAddress((void**)&dblp, g_dblpart);
    cudaGetSymbolAddress((void**)&dbl,  g_dbl);
    cudaGetSymbolAddress((void**)&delta,g_delta);
    cudaGetSymbolAddress((void**)&yg,   g_yg);
    cudaGetSymbolAddress((void**)&pA,   g_prodA);
    cudaGetSymbolAddress((void**)&he,   g_hend);
    cudaGetSymbolAddress((void**)&hi,   g_hinit);

    // G1: xr = x @ W_in^T   (4096x1024) x (4096x1024)^T -> 4096x4096
    sgemm_nt<<<dim3(2*DINNER/GBN, LSEQ/GBM, 1), 256>>>(
        x, DMODEL, W_in, DMODEL, xr, 2*DINNER,
        LSEQ, 2*DINNER, DMODEL, DMODEL, 0, nullptr, 0);

    // conv + silu -> xs
    conv_silu<<<(LSEQ*DINNER + 255)/256, 256>>>(xr, conv_w, conv_b, xs);

    // G2 (split-K x8): dblpart[z] = xs @ W_x^T partials  (N=96)
    sgemm_nt<<<dim3(1, LSEQ/GBM, KSPLIT), 256>>>(
        xs, DINNER, W_x, DINNER, dblp, DBLW,
        LSEQ, DBLW, DINNER, DINNER/KSPLIT, (size_t)LSEQ*DBLW, nullptr, 0);
    reduce_splitk<<<(LSEQ*DBLW + 255)/256, 256>>>(dblp, dbl, LSEQ*DBLW);

    // G3: delta = softplus(dt_in @ W_dt^T + b_dt)   (A = dbl[:, :64], lda=96)
    sgemm_nt<<<dim3(DINNER/GBN, LSEQ/GBM, 1), 256>>>(
        dbl, DBLW, W_dt, DTRANK, delta, DINNER,
        LSEQ, DINNER, DTRANK, DTRANK, 0, b_dt, 1);

    // selective scan (3 phases) -> yg (already gated by silu(res), +xs*D)
    scan_phaseA<<<dim3(DINNER/16, NCHUNK), 256>>>(delta, xs, dbl, A_log, pA, he);
    scan_phaseB<<<(DINNER*DSTATE + 255)/256, 256>>>(pA, he, hi);
    scan_phaseC<<<dim3(DINNER/16, NCHUNK), 256>>>(delta, xs, dbl, A_log, Dv, xr, hi, yg);

    // G4: out = yg @ W_out^T -> 4096x1024
    sgemm_nt<<<dim3(DMODEL/GBN, LSEQ/GBM, 1), 256>>>(
        yg, DINNER, W_out, DINNER, out, DMODEL,
        LSEQ, DMODEL, DINNER, DINNER, 0, nullptr, 0);
}

// round 3
// speedup vs baseline: 1.4043x; 1.4043x over previous
#include <cuda_runtime.h>
#include <cuda_bf16.h>
#include <cstdint>

// ---------------- problem constants ----------------
#define LSEQ    4096
#define DMODEL  1024
#define DINNER  2048
#define DCONV   4
#define DTRANK  64
#define DSTATE  16
#define DBLW    (DTRANK + 2*DSTATE)   // 96
#define CHUNK   128
#define NCHUNK  (LSEQ / CHUNK)        // 32
#define G2SPLIT 4

// ---------------- scratch (static device globals; zero-initialized) ----------------
__device__ float g_xr[(size_t)LSEQ * 2 * DINNER];          // [xi | res]
__device__ float g_xs[(size_t)LSEQ * DINNER];
__device__ float g_dblpart[(size_t)G2SPLIT * LSEQ * DBLW];
__device__ float g_dbl[(size_t)LSEQ * DBLW];
__device__ float g_delta[(size_t)LSEQ * DINNER];
__device__ float g_prodA[(size_t)NCHUNK * DINNER * DSTATE];
__device__ float g_hend [(size_t)NCHUNK * DINNER * DSTATE];
__device__ float g_hinit[(size_t)NCHUNK * DINNER * DSTATE];

// split-precision bf16 operands (128B-aligned for cp.async 16B)
__device__ __align__(128) __nv_bfloat16 g_xhi  [(size_t)LSEQ * DMODEL];
__device__ __align__(128) __nv_bfloat16 g_xlo  [(size_t)LSEQ * DMODEL];
__device__ __align__(128) __nv_bfloat16 g_winhi[(size_t)2*DINNER * DMODEL];
__device__ __align__(128) __nv_bfloat16 g_winlo[(size_t)2*DINNER * DMODEL];
__device__ __align__(128) __nv_bfloat16 g_wouthi[(size_t)DMODEL * DINNER];
__device__ __align__(128) __nv_bfloat16 g_woutlo[(size_t)DMODEL * DINNER];
__device__ __align__(128) __nv_bfloat16 g_yghi [(size_t)LSEQ * DINNER];
__device__ __align__(128) __nv_bfloat16 g_yglo [(size_t)LSEQ * DINNER];
__device__ __align__(128) __nv_bfloat16 g_xshi [(size_t)LSEQ * DINNER];
__device__ __align__(128) __nv_bfloat16 g_xslo [(size_t)LSEQ * DINNER];
// W_x padded to 128 rows (rows 96..127 stay zero from static init)
__device__ __align__(128) __nv_bfloat16 g_wxhi[(size_t)128 * DINNER];
__device__ __align__(128) __nv_bfloat16 g_wxlo[(size_t)128 * DINNER];

// ================= low-level helpers (non-arch-specific PTX only) =================
__device__ __forceinline__ uint32_t smem_u32(const void* p) {
    uint32_t a;
    asm("{ .reg .u64 t; cvta.to.shared.u64 t, %1; cvt.u32.u64 %0, t; }" : "=r"(a) : "l"(p));
    return a;
}
__device__ __forceinline__ void cp16(uint32_t dst, const void* src) {
    asm volatile("cp.async.cg.shared.global [%0], [%1], 16;"
                 :: "r"(dst), "l"(__cvta_generic_to_global(src)));
}
#define CP_COMMIT() asm volatile("cp.async.commit_group;" ::: "memory")
#define CP_WAIT1()  asm volatile("cp.async.wait_group 1;" ::: "memory")

#define LDSM4(r, a) asm volatile( \
    "ldmatrix.sync.aligned.m8n8.x4.shared.b16 {%0,%1,%2,%3}, [%4];" \
    : "=r"((r)[0]), "=r"((r)[1]), "=r"((r)[2]), "=r"((r)[3]) : "r"(a))

#define MMA_BF16(c, a, b) asm volatile( \
    "mma.sync.aligned.m16n8k16.row.col.f32.bf16.bf16.f32 " \
    "{%0,%1,%2,%3}, {%4,%5,%6,%7}, {%8,%9}, {%0,%1,%2,%3};" \
    : "+f"((c)[0]), "+f"((c)[1]), "+f"((c)[2]), "+f"((c)[3]) \
    : "r"((a)[0]), "r"((a)[1]), "r"((a)[2]), "r"((a)[3]), "r"((b)[0]), "r"((b)[1]))

// ================= bf16 split-precision GEMM (mma.sync path) =================
// C[M,N](+split-K partials) = (Ahi+Alo)[M,K] * (Bhi+Blo)[N,K]^T, fp32 acc.
// CTA tile 128x128xBK32, 8 warps (warp tile 32x64), 3-stage cp.async pipeline.
// SMEM tile rows padded 64B->80B: row addresses stride 80 mod 128 are distinct
// per 8 consecutive rows -> conflict-free ldmatrix.
#define TILE_B   10240            // 128 rows * 80B
#define STAGE_B  (4*TILE_B)       // Ahi,Alo,Bhi,Blo
#define GEMM_SMEM (3*STAGE_B)     // 122880

__global__ __launch_bounds__(256, 1) void gemm_bf16(
    const __nv_bfloat16* __restrict__ Ahi, const __nv_bfloat16* __restrict__ Alo,
    const __nv_bfloat16* __restrict__ Bhi, const __nv_bfloat16* __restrict__ Blo,
    float* __restrict__ C, int ldc, int Nvalid, int K,
    int kchunk, size_t splitStride)
{
    extern __shared__ __align__(128) char smem[];
    const uint32_t sbase = smem_u32(smem);
    const int tid  = threadIdx.x;
    const int wid  = tid >> 5;
    const int lane = tid & 31;
    const int rowBase = blockIdx.y * 128;
    const int colBase = blockIdx.x * 128;
    const int kbeg  = blockIdx.z * kchunk;
    const int niter = kchunk >> 5;
    C += (size_t)blockIdx.z * splitStride;

    const __nv_bfloat16* srcs[4] = {
        Ahi + (size_t)rowBase * K, Alo + (size_t)rowBase * K,
        Bhi + (size_t)colBase * K, Blo + (size_t)colBase * K };

    const int warp_row = wid & 3;   // 4 warps over M (32 rows each)
    const int warp_col = wid >> 2;  // 2 warps over N (64 cols each)
    // ldmatrix per-thread byte offsets inside a tile
    const uint32_t aoff = (uint32_t)((warp_row*32 + (lane & 15)) * 80 + (lane >> 4) * 16);
    const uint32_t boff = (uint32_t)((warp_col*64 + (lane >> 4)*8 + (lane & 7)) * 80
                                     + ((lane >> 3) & 1) * 16);

    float acc[2][8][4];
#pragma unroll
    for (int mt = 0; mt < 2; ++mt)
#pragma unroll
        for (int nt = 0; nt < 8; ++nt)
#pragma unroll
            for (int q = 0; q < 4; ++q) acc[mt][nt][q] = 0.f;

    auto load_stage = [&](int s) {
        const int kpos = kbeg + s * 32;
        const uint32_t db = sbase + (uint32_t)(s % 3) * STAGE_B;
#pragma unroll
        for (int tl = 0; tl < 4; ++tl) {
            const __nv_bfloat16* sp = srcs[tl];
#pragma unroll
            for (int q = 0; q < 2; ++q) {
                int i = tid + q * 256;        // 0..511
                int r = i >> 2, c = i & 3;
                cp16(db + (uint32_t)(tl * TILE_B + r * 80 + c * 16),
                     sp + (size_t)r * K + kpos + c * 8);
            }
        }
    };

    auto compute = [&](int s) {
        const uint32_t bb = sbase + (uint32_t)(s % 3) * STAGE_B;
#pragma unroll
        for (int kk = 0; kk < 2; ++kk) {
            uint32_t ah[2][4], al[2][4], bh[8][2], bl[8][2];
#pragma unroll
            for (int mt = 0; mt < 2; ++mt) {
                uint32_t ad = bb + aoff + (uint32_t)(mt * 1280 + kk * 32);
                LDSM4(ah[mt], ad);
                LDSM4(al[mt], ad + TILE_B);
            }
#pragma unroll
            for (int p = 0; p < 4; ++p) {
                uint32_t bd = bb + 2*TILE_B + boff + (uint32_t)(p * 1280 + kk * 32);
                uint32_t r[4];
                LDSM4(r, bd);
                bh[2*p][0] = r[0]; bh[2*p][1] = r[1]; bh[2*p+1][0] = r[2]; bh[2*p+1][1] = r[3];
                LDSM4(r, bd + TILE_B);
                bl[2*p][0] = r[0]; bl[2*p][1] = r[1]; bl[2*p+1][0] = r[2]; bl[2*p+1][1] = r[3];
            }
#pragma unroll
            for (int mt = 0; mt < 2; ++mt)
#pragma unroll
                for (int nt = 0; nt < 8; ++nt) {
                    MMA_BF16(acc[mt][nt], ah[mt], bh[nt]);
                    MMA_BF16(acc[mt][nt], ah[mt], bl[nt]);
                    MMA_BF16(acc[mt][nt], al[mt], bh[nt]);
                }
        }
    };

    load_stage(0); CP_COMMIT();
    load_stage(1); CP_COMMIT();

    for (int i = 0; i < niter; ++i) {
        CP_WAIT1();
        __syncthreads();
        if (i + 2 < niter) load_stage(i + 2);
        CP_COMMIT();
        compute(i);
    }

    // epilogue: direct stores (8B per thread per fragment row; 32B sectors full)
#pragma unroll
    for (int mt = 0; mt < 2; ++mt) {
#pragma unroll
        for (int nt = 0; nt < 8; ++nt) {
            int m0 = rowBase + warp_row*32 + mt*16 + (lane >> 2);
            int n0 = colBase + warp_col*64 + nt*8 + (lane & 3)*2;
            if (n0 < Nvalid) {
                *(float2*)&C[(size_t)m0 * ldc + n0] =
                    make_float2(acc[mt][nt][0], acc[mt][nt][1]);
                *(float2*)&C[(size_t)(m0 + 8) * ldc + n0] =
                    make_float2(acc[mt][nt][2], acc[mt][nt][3]);
            }
        }
    }
}

// ---------------- fp32 -> (bf16 hi, bf16 lo) split ----------------
__global__ void split_bf16(const float* __restrict__ in,
                           __nv_bfloat16* __restrict__ hi,
                           __nv_bfloat16* __restrict__ lo, int n)
{
    int i = blockIdx.x * blockDim.x + threadIdx.x;
    if (i >= n) return;
    float v = in[i];
    __nv_bfloat16 h = __float2bfloat16(v);
    hi[i] = h;
    lo[i] = __float2bfloat16(v - __bfloat162float(h));
}

// ---------------- split-K partial reduce ----------------
__global__ void reduce_nz(const float* __restrict__ part, float* __restrict__ out,
                          int n, int nz)
{
    int i = blockIdx.x * blockDim.x + threadIdx.x;
    if (i >= n) return;
    float s = 0.f;
    for (int z = 0; z < nz; ++z) s += part[(size_t)z * n + i];
    out[i] = s;
}

// ---------------- fp32 SGEMM (kept for small G3) ----------------
#define GBM 128
#define GBN 128
#define GBK 8

__global__ __launch_bounds__(256) void sgemm_nt(
    const float* __restrict__ A, int lda,
    const float* __restrict__ B, int ldb,
    float* __restrict__ C, int ldc,
    int M, int N, int K,
    const float* __restrict__ bias, int act)
{
    __shared__ float As[GBK][GBM];
    __shared__ float Bs[GBK][GBN];

    const int tid = threadIdx.x;
    const int rowBase = blockIdx.y * GBM;
    const int colBase = blockIdx.x * GBN;

    const int lr = tid >> 1;
    const int lc = (tid & 1) * 4;

    const float* Aptr = A + (size_t)(rowBase + lr) * lda + lc;
    const float* Bptr = B + (size_t)(colBase + lr) * ldb + lc;
    const bool avalid = (rowBase + lr) < M;
    const bool bvalid = (colBase + lr) < N;

    const int tx = tid & 15;
    const int ty = tid >> 4;

    float acc[8][8];
#pragma unroll
    for (int i = 0; i < 8; ++i)
#pragma unroll
        for (int j = 0; j < 8; ++j) acc[i][j] = 0.f;

    for (int k0 = 0; k0 < K; k0 += GBK) {
        float4 av = avalid ? *(const float4*)(Aptr + k0) : make_float4(0.f,0.f,0.f,0.f);
        float4 bv = bvalid ? *(const float4*)(Bptr + k0) : make_float4(0.f,0.f,0.f,0.f);
        __syncthreads();
        As[lc+0][lr] = av.x; As[lc+1][lr] = av.y; As[lc+2][lr] = av.z; As[lc+3][lr] = av.w;
        Bs[lc+0][lr] = bv.x; Bs[lc+1][lr] = bv.y; Bs[lc+2][lr] = bv.z; Bs[lc+3][lr] = bv.w;
        __syncthreads();
#pragma unroll
        for (int kk = 0; kk < GBK; ++kk) {
            float4 a0 = *(const float4*)&As[kk][ty*4];
            float4 a1 = *(const float4*)&As[kk][64 + ty*4];
            float4 b0 = *(const float4*)&Bs[kk][tx*4];
            float4 b1 = *(const float4*)&Bs[kk][64 + tx*4];
            float ra[8] = {a0.x,a0.y,a0.z,a0.w,a1.x,a1.y,a1.z,a1.w};
            float rb[8] = {b0.x,b0.y,b0.z,b0.w,b1.x,b1.y,b1.z,b1.w};
#pragma unroll
            for (int i = 0; i < 8; ++i)
#pragma unroll
                for (int j = 0; j < 8; ++j)
                    acc[i][j] = fmaf(ra[i], rb[j], acc[i][j]);
        }
    }

#pragma unroll
    for (int i = 0; i < 8; ++i) {
        int row = rowBase + ((i < 4) ? (ty*4 + i) : (64 + ty*4 + i - 4));
        if (row >= M) continue;
#pragma unroll
        for (int j = 0; j < 8; ++j) {
            int col = colBase + ((j < 4) ? (tx*4 + j) : (64 + tx*4 + j - 4));
            if (col >= N) continue;
            float v = acc[i][j];
            if (bias) v += bias[col];
            if (act == 1) v = (v > 20.f) ? v : log1pf(__expf(v));  // softplus
            C[(size_t)row * ldc + col] = v;
        }
    }
}

// ---------------- causal depthwise conv(k=4) + bias + silu (+bf16 split out) ----------------
__global__ void conv_silu(const float* __restrict__ xr,
                          const float* __restrict__ cw,
                          const float* __restrict__ cb,
                          float* __restrict__ xs,
                          __nv_bfloat16* __restrict__ xshi,
                          __nv_bfloat16* __restrict__ xslo)
{
    int idx = blockIdx.x * blockDim.x + threadIdx.x;
    if (idx >= LSEQ * DINNER) return;
    int t = idx / DINNER;
    int d = idx - t * DINNER;
    float acc = cb[d];
#pragma unroll
    for (int k = 0; k < DCONV; ++k) {
        int tt = t - (DCONV - 1) + k;
        if (tt >= 0) acc = fmaf(cw[d * DCONV + k], xr[(size_t)tt * (2*DINNER) + d], acc);
    }
    float sig = 1.f / (1.f + __expf(-acc));
    float v = acc * sig;
    xs[idx] = v;
    __nv_bfloat16 h = __float2bfloat16(v);
    xshi[idx] = h;
    xslo[idx] = __float2bfloat16(v - __bfloat162float(h));
}

// ---------------- selective scan: 3-phase chunked ----------------
__global__ __launch_bounds__(256) void scan_phaseA(
    const float* __restrict__ delta, const float* __restrict__ xs,
    const float* __restrict__ dbl, const float* __restrict__ A_log,
    float* __restrict__ prodA, float* __restrict__ hend)
{
    const int tid = threadIdx.x;
    const int n  = tid & 15;
    const int d  = blockIdx.x * 16 + (tid >> 4);
    const int chunk = blockIdx.y;
    const float Adn = -__expf(A_log[d * DSTATE + n]);
    const float* Bp = dbl + DTRANK;

    float h = 0.f, pA = 1.f;
    const int t0 = chunk * CHUNK;
#pragma unroll 4
    for (int t = t0; t < t0 + CHUNK; ++t) {
        float dl = delta[(size_t)t * DINNER + d];
        float xv = xs[(size_t)t * DINNER + d];
        float b  = Bp[(size_t)t * DBLW + n];
        float a  = __expf(dl * Adn);
        h  = fmaf(a, h, dl * xv * b);
        pA *= a;
    }
    int idx = chunk * (DINNER * DSTATE) + d * DSTATE + n;
    prodA[idx] = pA;
    hend[idx]  = h;
}

__global__ void scan_phaseB(const float* __restrict__ prodA,
                            const float* __restrict__ hend,
                            float* __restrict__ hinit)
{
    int i = blockIdx.x * blockDim.x + threadIdx.x;
    if (i >= DINNER * DSTATE) return;
    float H = 0.f;
#pragma unroll
    for (int c = 0; c < NCHUNK; ++c) {
        int idx = c * (DINNER * DSTATE) + i;
        hinit[idx] = H;
        H = fmaf(prodA[idx], H, hend[idx]);
    }
}

__global__ __launch_bounds__(256) void scan_phaseC(
    const float* __restrict__ delta, const float* __restrict__ xs,
    const float* __restrict__ dbl, const float* __restrict__ A_log,
    const float* __restrict__ Dv, const float* __restrict__ xr,
    const float* __restrict__ hinit,
    __nv_bfloat16* __restrict__ yghi, __nv_bfloat16* __restrict__ yglo)
{
    const int tid = threadIdx.x;
    const int n  = tid & 15;
    const int d  = blockIdx.x * 16 + (tid >> 4);
    const int chunk = blockIdx.y;
    const float Adn = -__expf(A_log[d * DSTATE + n]);
    const float Dd  = Dv[d];
    const float* Bp = dbl + DTRANK;
    const float* Cp = dbl + DTRANK + DSTATE;

    float h = hinit[chunk * (DINNER * DSTATE) + d * DSTATE + n];
    const int t0 = chunk * CHUNK;
#pragma unroll 2
    for (int t = t0; t < t0 + CHUNK; ++t) {
        float dl = delta[(size_t)t * DINNER + d];
        float xv = xs[(size_t)t * DINNER + d];
        float b  = Bp[(size_t)t * DBLW + n];
        float c  = Cp[(size_t)t * DBLW + n];
        float a  = __expf(dl * Adn);
        h = fmaf(a, h, dl * xv * b);
        float p = h * c;
        p += __shfl_xor_sync(0xffffffffu, p, 1, 16);
        p += __shfl_xor_sync(0xffffffffu, p, 2, 16);
        p += __shfl_xor_sync(0xffffffffu, p, 4, 16);
        p += __shfl_xor_sync(0xffffffffu, p, 8, 16);
        if (n == 0) {
            float r   = xr[(size_t)t * (2*DINNER) + DINNER + d];
            float sig = 1.f / (1.f + __expf(-r));
            float yv  = (p + xv * Dd) * (r * sig);
            __nv_bfloat16 hh = __float2bfloat16(yv);
            yghi[(size_t)t * DINNER + d] = hh;
            yglo[(size_t)t * DINNER + d] = __float2bfloat16(yv - __bfloat162float(hh));
        }
    }
}

// ---------------- launcher ----------------
extern "C" void kernel_launch(void* const* d_in, const int* in_sizes, int n_in,
                              void* d_out, int out_size)
{
    const float* x      = (const float*)d_in[0];
    const float* W_in   = (const float*)d_in[1];
    const float* conv_w = (const float*)d_in[2];
    const float* conv_b = (const float*)d_in[3];
    const float* W_x    = (const float*)d_in[4];
    const float* W_dt   = (const float*)d_in[5];
    const float* b_dt   = (const float*)d_in[6];
    const float* A_log  = (const float*)d_in[7];
    const float* Dv     = (const float*)d_in[8];
    const float* W_out  = (const float*)d_in[9];
    float* out = (float*)d_out;

    float *xr, *xs, *dblp, *dbl, *delta, *pA, *he, *hi;
    cudaGetSymbolAddress((void**)&xr,   g_xr);
    cudaGetSymbolAddress((void**)&xs,   g_xs);
    cudaGetSymbolAddress((void**)&dblp, g_dblpart);
    cudaGetSymbolAddress((void**)&dbl,  g_dbl);
    cudaGetSymbolAddress((void**)&delta,g_delta);
    cudaGetSymbolAddress((void**)&pA,   g_prodA);
    cudaGetSymbolAddress((void**)&he,   g_hend);
    cudaGetSymbolAddress((void**)&hi,   g_hinit);

    __nv_bfloat16 *xhi, *xlo, *winhi, *winlo, *wouthi, *woutlo, *yghi, *yglo;
    __nv_bfloat16 *xshi, *xslo, *wxhi, *wxlo;
    cudaGetSymbolAddress((void**)&xhi,   g_xhi);
    cudaGetSymbolAddress((void**)&xlo,   g_xlo);
    cudaGetSymbolAddress((void**)&winhi, g_winhi);
    cudaGetSymbolAddress((void**)&winlo, g_winlo);
    cudaGetSymbolAddress((void**)&wouthi,g_wouthi);
    cudaGetSymbolAddress((void**)&woutlo,g_woutlo);
    cudaGetSymbolAddress((void**)&yghi,  g_yghi);
    cudaGetSymbolAddress((void**)&yglo,  g_yglo);
    cudaGetSymbolAddress((void**)&xshi,  g_xshi);
    cudaGetSymbolAddress((void**)&xslo,  g_xslo);
    cudaGetSymbolAddress((void**)&wxhi,  g_wxhi);
    cudaGetSymbolAddress((void**)&wxlo,  g_wxlo);

    cudaFuncSetAttribute(gemm_bf16, cudaFuncAttributeMaxDynamicSharedMemorySize, GEMM_SMEM);

    // splits
    split_bf16<<<(LSEQ*DMODEL + 255)/256, 256>>>(x, xhi, xlo, LSEQ*DMODEL);
    split_bf16<<<(2*DINNER*DMODEL + 255)/256, 256>>>(W_in, winhi, winlo, 2*DINNER*DMODEL);
    split_bf16<<<(DMODEL*DINNER + 255)/256, 256>>>(W_out, wouthi, woutlo, DMODEL*DINNER);
    split_bf16<<<(DBLW*DINNER + 255)/256, 256>>>(W_x, wxhi, wxlo, DBLW*DINNER);  // rows 96..127 stay 0

    // G1 (mma): xr = x @ W_in^T -> 4096 x 4096
    gemm_bf16<<<dim3(2*DINNER/128, LSEQ/128, 1), 256, GEMM_SMEM>>>(
        xhi, xlo, winhi, winlo, xr, 2*DINNER, 2*DINNER, DMODEL, DMODEL, 0);

    // conv + silu -> xs (fp32 + bf16 hi/lo)
    conv_silu<<<(LSEQ*DINNER + 255)/256, 256>>>(xr, conv_w, conv_b, xs, xshi, xslo);

    // G2 (mma, split-K x4): dbl = xs @ W_x^T (N=96, padded to 128)
    gemm_bf16<<<dim3(1, LSEQ/128, G2SPLIT), 256, GEMM_SMEM>>>(
        xshi, xslo, wxhi, wxlo, dblp, DBLW, DBLW, DINNER, DINNER/G2SPLIT,
        (size_t)LSEQ*DBLW);
    reduce_nz<<<(LSEQ*DBLW + 255)/256, 256>>>(dblp, dbl, LSEQ*DBLW, G2SPLIT);

    // G3 (fp32): delta = softplus(dt_in @ W_dt^T + b_dt)
    sgemm_nt<<<dim3(DINNER/GBN, LSEQ/GBM, 1), 256>>>(
        dbl, DBLW, W_dt, DTRANK, delta, DINNER,
        LSEQ, DINNER, DTRANK, b_dt, 1);

    // selective scan (3 phases); phase C emits split-bf16 yg
    scan_phaseA<<<dim3(DINNER/16, NCHUNK), 256>>>(delta, xs, dbl, A_log, pA, he);
    scan_phaseB<<<(DINNER*DSTATE + 255)/256, 256>>>(pA, he, hi);
    scan_phaseC<<<dim3(DINNER/16, NCHUNK), 256>>>(delta, xs, dbl, A_log, Dv, xr, hi, yghi, yglo);

    // G4 (mma): out = yg @ W_out^T -> 4096 x 1024
    gemm_bf16<<<dim3(DMODEL/128, LSEQ/128, 1), 256, GEMM_SMEM>>>(
        yghi, yglo, wouthi, woutlo, out, DMODEL, DMODEL, DINNER, DINNER, 0);
}

// round 4
// speedup vs baseline: 2.1171x; 1.5076x over previous
#include <cuda_runtime.h>
#include <cuda_fp16.h>
#include <cuda_bf16.h>
#include <cstdint>

// ---------------- problem constants ----------------
#define LSEQ    4096
#define DMODEL  1024
#define DINNER  2048
#define DCONV   4
#define DTRANK  64
#define DSTATE  16
#define DBLW    (DTRANK + 2*DSTATE)   // 96
#define CHUNK   128
#define NCHUNK  (LSEQ / CHUNK)        // 32
#define G2SPLIT 4

// ---------------- scratch (static device globals; zero-initialized) ----------------
__device__ float g_xr[(size_t)LSEQ * 2 * DINNER];          // [xi | res]
__device__ float g_xs[(size_t)LSEQ * DINNER];
__device__ float g_dblpart[(size_t)G2SPLIT * LSEQ * DBLW];
__device__ float g_dbl[(size_t)LSEQ * DBLW];
__device__ float g_delta[(size_t)LSEQ * DINNER];
__device__ float g_prodA[(size_t)NCHUNK * DINNER * DSTATE];
__device__ float g_hend [(size_t)NCHUNK * DINNER * DSTATE];
__device__ float g_hinit[(size_t)NCHUNK * DINNER * DSTATE];

// fp16 operands (128B-aligned for cp.async 16B)
__device__ __align__(128) __half g_xh  [(size_t)LSEQ * DMODEL];
__device__ __align__(128) __half g_winh[(size_t)2*DINNER * DMODEL];
__device__ __align__(128) __half g_wouth[(size_t)DMODEL * DINNER];
__device__ __align__(128) __half g_ygh [(size_t)LSEQ * DINNER];
__device__ __align__(128) __half g_xsh [(size_t)LSEQ * DINNER];
// W_x padded to 128 rows (rows 96..127 stay zero from static init)
__device__ __align__(128) __half g_wxh[(size_t)128 * DINNER];

// ================= low-level helpers (non-arch-specific PTX only) =================
__device__ __forceinline__ uint32_t smem_u32(const void* p) {
    uint32_t a;
    asm("{ .reg .u64 t; cvta.to.shared.u64 t, %1; cvt.u32.u64 %0, t; }" : "=r"(a) : "l"(p));
    return a;
}
__device__ __forceinline__ void cp16(uint32_t dst, const void* src) {
    asm volatile("cp.async.cg.shared.global [%0], [%1], 16;"
                 :: "r"(dst), "l"(__cvta_generic_to_global(src)));
}
#define CP_COMMIT() asm volatile("cp.async.commit_group;" ::: "memory")
#define CP_WAIT2()  asm volatile("cp.async.wait_group 2;" ::: "memory")

#define LDSM4(r, a) asm volatile( \
    "ldmatrix.sync.aligned.m8n8.x4.shared.b16 {%0,%1,%2,%3}, [%4];" \
    : "=r"((r)[0]), "=r"((r)[1]), "=r"((r)[2]), "=r"((r)[3]) : "r"(a))

#define MMA_F16(c, a, b) asm volatile( \
    "mma.sync.aligned.m16n8k16.row.col.f32.f16.f16.f32 " \
    "{%0,%1,%2,%3}, {%4,%5,%6,%7}, {%8,%9}, {%0,%1,%2,%3};" \
    : "+f"((c)[0]), "+f"((c)[1]), "+f"((c)[2]), "+f"((c)[3]) \
    : "r"((a)[0]), "r"((a)[1]), "r"((a)[2]), "r"((a)[3]), "r"((b)[0]), "r"((b)[1]))

// ================= fp16 GEMM (mma.sync, single product) =================
// C[M,N](+split-K partials) = A[M,K] * B[N,K]^T, fp32 acc.
// CTA tile 128x128xBK32, 8 warps (warp tile 32x64), 4-stage cp.async pipeline.
// SMEM rows padded 64B->80B: 80 mod 128 gives 8 distinct 16B slots per 8 rows
// -> conflict-free ldmatrix.
#define TILE_B   10240            // 128 rows * 80B
#define STAGE_B  (2*TILE_B)       // A,B
#define NSTAGE   4
#define GEMM_SMEM (NSTAGE*STAGE_B) // 81920

__global__ __launch_bounds__(256, 2) void gemm_f16(
    const __half* __restrict__ A, const __half* __restrict__ B,
    float* __restrict__ C, int ldc, int Nvalid, int K,
    int kchunk, size_t splitStride)
{
    extern __shared__ __align__(128) char smem[];
    const uint32_t sbase = smem_u32(smem);
    const int tid  = threadIdx.x;
    const int wid  = tid >> 5;
    const int lane = tid & 31;
    const int rowBase = blockIdx.y * 128;
    const int colBase = blockIdx.x * 128;
    const int kbeg  = blockIdx.z * kchunk;
    const int niter = kchunk >> 5;
    C += (size_t)blockIdx.z * splitStride;

    const __half* srcA = A + (size_t)rowBase * K;
    const __half* srcB = B + (size_t)colBase * K;

    const int warp_row = wid & 3;   // 4 warps over M (32 rows each)
    const int warp_col = wid >> 2;  // 2 warps over N (64 cols each)
    const uint32_t aoff = (uint32_t)((warp_row*32 + (lane & 15)) * 80 + (lane >> 4) * 16);
    const uint32_t boff = (uint32_t)((warp_col*64 + (lane >> 4)*8 + (lane & 7)) * 80
                                     + ((lane >> 3) & 1) * 16);

    float acc[2][8][4];
#pragma unroll
    for (int mt = 0; mt < 2; ++mt)
#pragma unroll
        for (int nt = 0; nt < 8; ++nt)
#pragma unroll
            for (int q = 0; q < 4; ++q) acc[mt][nt][q] = 0.f;

    auto load_stage = [&](int s) {
        const int kpos = kbeg + s * 32;
        const uint32_t db = sbase + (uint32_t)(s & (NSTAGE-1)) * STAGE_B;
#pragma unroll
        for (int q = 0; q < 2; ++q) {
            int i = tid + q * 256;        // 0..511
            int r = i >> 2, c = i & 3;
            cp16(db + (uint32_t)(r * 80 + c * 16),          srcA + (size_t)r * K + kpos + c * 8);
            cp16(db + (uint32_t)(TILE_B + r * 80 + c * 16), srcB + (size_t)r * K + kpos + c * 8);
        }
    };

    auto compute = [&](int s) {
        const uint32_t bb = sbase + (uint32_t)(s & (NSTAGE-1)) * STAGE_B;
#pragma unroll
        for (int kk = 0; kk < 2; ++kk) {
            uint32_t a[2][4], b[8][2];
#pragma unroll
            for (int mt = 0; mt < 2; ++mt)
                LDSM4(a[mt], bb + aoff + (uint32_t)(mt * 1280 + kk * 32));
#pragma unroll
            for (int p = 0; p < 4; ++p) {
                uint32_t r[4];
                LDSM4(r, bb + TILE_B + boff + (uint32_t)(p * 1280 + kk * 32));
                b[2*p][0] = r[0]; b[2*p][1] = r[1]; b[2*p+1][0] = r[2]; b[2*p+1][1] = r[3];
            }
#pragma unroll
            for (int mt = 0; mt < 2; ++mt)
#pragma unroll
                for (int nt = 0; nt < 8; ++nt)
                    MMA_F16(acc[mt][nt], a[mt], b[nt]);
        }
    };

    load_stage(0); CP_COMMIT();
    load_stage(1); CP_COMMIT();
    load_stage(2); CP_COMMIT();

    for (int i = 0; i < niter; ++i) {
        CP_WAIT2();
        __syncthreads();
        if (i + 3 < niter) load_stage(i + 3);
        CP_COMMIT();
        compute(i);
        __syncthreads();
    }

    // epilogue: direct stores (8B per thread per fragment row)
#pragma unroll
    for (int mt = 0; mt < 2; ++mt) {
#pragma unroll
        for (int nt = 0; nt < 8; ++nt) {
            int m0 = rowBase + warp_row*32 + mt*16 + (lane >> 2);
            int n0 = colBase + warp_col*64 + nt*8 + (lane & 3)*2;
            if (n0 < Nvalid) {
                *(float2*)&C[(size_t)m0 * ldc + n0] =
                    make_float2(acc[mt][nt][0], acc[mt][nt][1]);
                *(float2*)&C[(size_t)(m0 + 8) * ldc + n0] =
                    make_float2(acc[mt][nt][2], acc[mt][nt][3]);
            }
        }
    }
}

// ---------------- fp32 -> fp16 convert ----------------
__global__ void cvt_f16(const float* __restrict__ in, __half* __restrict__ out, int n)
{
    int i = blockIdx.x * blockDim.x + threadIdx.x;
    if (i >= n) return;
    out[i] = __float2half(in[i]);
}

// ---------------- split-K partial reduce ----------------
__global__ void reduce_nz(const float* __restrict__ part, float* __restrict__ out,
                          int n, int nz)
{
    int i = blockIdx.x * blockDim.x + threadIdx.x;
    if (i >= n) return;
    float s = 0.f;
    for (int z = 0; z < nz; ++z) s += part[(size_t)z * n + i];
    out[i] = s;
}

// ---------------- fp32 SGEMM (kept for small G3) ----------------
#define GBM 128
#define GBN 128
#define GBK 8

__global__ __launch_bounds__(256) void sgemm_nt(
    const float* __restrict__ A, int lda,
    const float* __restrict__ B, int ldb,
    float* __restrict__ C, int ldc,
    int M, int N, int K,
    const float* __restrict__ bias, int act)
{
    __shared__ float As[GBK][GBM];
    __shared__ float Bs[GBK][GBN];

    const int tid = threadIdx.x;
    const int rowBase = blockIdx.y * GBM;
    const int colBase = blockIdx.x * GBN;

    const int lr = tid >> 1;
    const int lc = (tid & 1) * 4;

    const float* Aptr = A + (size_t)(rowBase + lr) * lda + lc;
    const float* Bptr = B + (size_t)(colBase + lr) * ldb + lc;
    const bool avalid = (rowBase + lr) < M;
    const bool bvalid = (colBase + lr) < N;

    const int tx = tid & 15;
    const int ty = tid >> 4;

    float acc[8][8];
#pragma unroll
    for (int i = 0; i < 8; ++i)
#pragma unroll
        for (int j = 0; j < 8; ++j) acc[i][j] = 0.f;

    for (int k0 = 0; k0 < K; k0 += GBK) {
        float4 av = avalid ? *(const float4*)(Aptr + k0) : make_float4(0.f,0.f,0.f,0.f);
        float4 bv = bvalid ? *(const float4*)(Bptr + k0) : make_float4(0.f,0.f,0.f,0.f);
        __syncthreads();
        As[lc+0][lr] = av.x; As[lc+1][lr] = av.y; As[lc+2][lr] = av.z; As[lc+3][lr] = av.w;
        Bs[lc+0][lr] = bv.x; Bs[lc+1][lr] = bv.y; Bs[lc+2][lr] = bv.z; Bs[lc+3][lr] = bv.w;
        __syncthreads();
#pragma unroll
        for (int kk = 0; kk < GBK; ++kk) {
            float4 a0 = *(const float4*)&As[kk][ty*4];
            float4 a1 = *(const float4*)&As[kk][64 + ty*4];
            float4 b0 = *(const float4*)&Bs[kk][tx*4];
            float4 b1 = *(const float4*)&Bs[kk][64 + tx*4];
            float ra[8] = {a0.x,a0.y,a0.z,a0.w,a1.x,a1.y,a1.z,a1.w};
            float rb[8] = {b0.x,b0.y,b0.z,b0.w,b1.x,b1.y,b1.z,b1.w};
#pragma unroll
            for (int i = 0; i < 8; ++i)
#pragma unroll
                for (int j = 0; j < 8; ++j)
                    acc[i][j] = fmaf(ra[i], rb[j], acc[i][j]);
        }
    }

#pragma unroll
    for (int i = 0; i < 8; ++i) {
        int row = rowBase + ((i < 4) ? (ty*4 + i) : (64 + ty*4 + i - 4));
        if (row >= M) continue;
#pragma unroll
        for (int j = 0; j < 8; ++j) {
            int col = colBase + ((j < 4) ? (tx*4 + j) : (64 + tx*4 + j - 4));
            if (col >= N) continue;
            float v = acc[i][j];
            if (bias) v += bias[col];
            if (act == 1) v = (v > 20.f) ? v : log1pf(__expf(v));  // softplus
            C[(size_t)row * ldc + col] = v;
        }
    }
}

// ---------------- causal depthwise conv(k=4) + bias + silu (+fp16 out) ----------------
__global__ void conv_silu(const float* __restrict__ xr,
                          const float* __restrict__ cw,
                          const float* __restrict__ cb,
                          float* __restrict__ xs,
                          __half* __restrict__ xsh)
{
    int idx = blockIdx.x * blockDim.x + threadIdx.x;
    if (idx >= LSEQ * DINNER) return;
    int t = idx / DINNER;
    int d = idx - t * DINNER;
    float acc = cb[d];
#pragma unroll
    for (int k = 0; k < DCONV; ++k) {
        int tt = t - (DCONV - 1) + k;
        if (tt >= 0) acc = fmaf(cw[d * DCONV + k], xr[(size_t)tt * (2*DINNER) + d], acc);
    }
    float sig = 1.f / (1.f + __expf(-acc));
    float v = acc * sig;
    xs[idx] = v;
    xsh[idx] = __float2half(v);
}

// ---------------- selective scan: 3-phase chunked ----------------
__global__ __launch_bounds__(256) void scan_phaseA(
    const float* __restrict__ delta, const float* __restrict__ xs,
    const float* __restrict__ dbl, const float* __restrict__ A_log,
    float* __restrict__ prodA, float* __restrict__ hend)
{
    const int tid = threadIdx.x;
    const int n  = tid & 15;
    const int d  = blockIdx.x * 16 + (tid >> 4);
    const int chunk = blockIdx.y;
    const float Adn = -__expf(A_log[d * DSTATE + n]);
    const float* Bp = dbl + DTRANK;

    float h = 0.f, pA = 1.f;
    const int t0 = chunk * CHUNK;
#pragma unroll 4
    for (int t = t0; t < t0 + CHUNK; ++t) {
        float dl = delta[(size_t)t * DINNER + d];
        float xv = xs[(size_t)t * DINNER + d];
        float b  = Bp[(size_t)t * DBLW + n];
        float a  = __expf(dl * Adn);
        h  = fmaf(a, h, dl * xv * b);
        pA *= a;
    }
    int idx = chunk * (DINNER * DSTATE) + d * DSTATE + n;
    prodA[idx] = pA;
    hend[idx]  = h;
}

__global__ void scan_phaseB(const float* __restrict__ prodA,
                            const float* __restrict__ hend,
                            float* __restrict__ hinit)
{
    int i = blockIdx.x * blockDim.x + threadIdx.x;
    if (i >= DINNER * DSTATE) return;
    float H = 0.f;
#pragma unroll
    for (int c = 0; c < NCHUNK; ++c) {
        int idx = c * (DINNER * DSTATE) + i;
        hinit[idx] = H;
        H = fmaf(prodA[idx], H, hend[idx]);
    }
}

__global__ __launch_bounds__(256) void scan_phaseC(
    const float* __restrict__ delta, const float* __restrict__ xs,
    const float* __restrict__ dbl, const float* __restrict__ A_log,
    const float* __restrict__ Dv, const float* __restrict__ xr,
    const float* __restrict__ hinit,
    __half* __restrict__ ygh)
{
    const int tid = threadIdx.x;
    const int n  = tid & 15;
    const int d  = blockIdx.x * 16 + (tid >> 4);
    const int chunk = blockIdx.y;
    const float Adn = -__expf(A_log[d * DSTATE + n]);
    const float Dd  = Dv[d];
    const float* Bp = dbl + DTRANK;
    const float* Cp = dbl + DTRANK + DSTATE;

    float h = hinit[chunk * (DINNER * DSTATE) + d * DSTATE + n];
    const int t0 = chunk * CHUNK;
#pragma unroll 2
    for (int t = t0; t < t0 + CHUNK; ++t) {
        float dl = delta[(size_t)t * DINNER + d];
        float xv = xs[(size_t)t * DINNER + d];
        float b  = Bp[(size_t)t * DBLW + n];
        float c  = Cp[(size_t)t * DBLW + n];
        float a  = __expf(dl * Adn);
        h = fmaf(a, h, dl * xv * b);
        float p = h * c;
        p += __shfl_xor_sync(0xffffffffu, p, 1, 16);
        p += __shfl_xor_sync(0xffffffffu, p, 2, 16);
        p += __shfl_xor_sync(0xffffffffu, p, 4, 16);
        p += __shfl_xor_sync(0xffffffffu, p, 8, 16);
        if (n == 0) {
            float r   = xr[(size_t)t * (2*DINNER) + DINNER + d];
            float sig = 1.f / (1.f + __expf(-r));
            float yv  = (p + xv * Dd) * (r * sig);
            ygh[(size_t)t * DINNER + d] = __float2half(yv);
        }
    }
}

// ---------------- launcher ----------------
extern "C" void kernel_launch(void* const* d_in, const int* in_sizes, int n_in,
                              void* d_out, int out_size)
{
    const float* x      = (const float*)d_in[0];
    const float* W_in   = (const float*)d_in[1];
    const float* conv_w = (const float*)d_in[2];
    const float* conv_b = (const float*)d_in[3];
    const float* W_x    = (const float*)d_in[4];
    const float* W_dt   = (const float*)d_in[5];
    const float* b_dt   = (const float*)d_in[6];
    const float* A_log  = (const float*)d_in[7];
    const float* Dv     = (const float*)d_in[8];
    const float* W_out  = (const float*)d_in[9];
    float* out = (float*)d_out;

    float *xr, *xs, *dblp, *dbl, *delta, *pA, *he, *hi;
    cudaGetSymbolAddress((void**)&xr,   g_xr);
    cudaGetSymbolAddress((void**)&xs,   g_xs);
    cudaGetSymbolAddress((void**)&dblp, g_dblpart);
    cudaGetSymbolAddress((void**)&dbl,  g_dbl);
    cudaGetSymbolAddress((void**)&delta,g_delta);
    cudaGetSymbolAddress((void**)&pA,   g_prodA);
    cudaGetSymbolAddress((void**)&he,   g_hend);
    cudaGetSymbolAddress((void**)&hi,   g_hinit);

    __half *xh, *winh, *wouth, *ygh, *xsh, *wxh;
    cudaGetSymbolAddress((void**)&xh,    g_xh);
    cudaGetSymbolAddress((void**)&winh,  g_winh);
    cudaGetSymbolAddress((void**)&wouth, g_wouth);
    cudaGetSymbolAddress((void**)&ygh,   g_ygh);
    cudaGetSymbolAddress((void**)&xsh,   g_xsh);
    cudaGetSymbolAddress((void**)&wxh,   g_wxh);

    cudaFuncSetAttribute(gemm_f16, cudaFuncAttributeMaxDynamicSharedMemorySize, GEMM_SMEM);

    // fp32 -> fp16 converts
    cvt_f16<<<(LSEQ*DMODEL + 255)/256, 256>>>(x, xh, LSEQ*DMODEL);
    cvt_f16<<<(2*DINNER*DMODEL + 255)/256, 256>>>(W_in, winh, 2*DINNER*DMODEL);
    cvt_f16<<<(DMODEL*DINNER + 255)/256, 256>>>(W_out, wouth, DMODEL*DINNER);
    cvt_f16<<<(DBLW*DINNER + 255)/256, 256>>>(W_x, wxh, DBLW*DINNER);  // rows 96..127 stay 0

    // G1 (mma): xr = x @ W_in^T -> 4096 x 4096
    gemm_f16<<<dim3(2*DINNER/128, LSEQ/128, 1), 256, GEMM_SMEM>>>(
        xh, winh, xr, 2*DINNER, 2*DINNER, DMODEL, DMODEL, 0);

    // conv + silu -> xs (fp32 + fp16)
    conv_silu<<<(LSEQ*DINNER + 255)/256, 256>>>(xr, conv_w, conv_b, xs, xsh);

    // G2 (mma, split-K x4): dbl = xs @ W_x^T (N=96, padded to 128)
    gemm_f16<<<dim3(1, LSEQ/128, G2SPLIT), 256, GEMM_SMEM>>>(
        xsh, wxh, dblp, DBLW, DBLW, DINNER, DINNER/G2SPLIT, (size_t)LSEQ*DBLW);
    reduce_nz<<<(LSEQ*DBLW + 255)/256, 256>>>(dblp, dbl, LSEQ*DBLW, G2SPLIT);

    // G3 (fp32): delta = softplus(dt_in @ W_dt^T + b_dt)
    sgemm_nt<<<dim3(DINNER/GBN, LSEQ/GBM, 1), 256>>>(
        dbl, DBLW, W_dt, DTRANK, delta, DINNER,
        LSEQ, DINNER, DTRANK, b_dt, 1);

    // selective scan (3 phases); phase C emits fp16 yg
    scan_phaseA<<<dim3(DINNER/16, NCHUNK), 256>>>(delta, xs, dbl, A_log, pA, he);
    scan_phaseB<<<(DINNER*DSTATE + 255)/256, 256>>>(pA, he, hi);
    scan_phaseC<<<dim3(DINNER/16, NCHUNK), 256>>>(delta, xs, dbl, A_log, Dv, xr, hi, ygh);

    // G4 (mma): out = yg @ W_out^T -> 4096 x 1024
    gemm_f16<<<dim3(DMODEL/128, LSEQ/128, 1), 256, GEMM_SMEM>>>(
        ygh, wouth, out, DMODEL, DMODEL, DINNER, DINNER, 0);
}

// round 6
// speedup vs baseline: 2.1645x; 1.0224x over previous
#include <cuda_runtime.h>
#include <cuda_fp16.h>
#include <cuda_bf16.h>
#include <cstdint>

// ---------------- problem constants ----------------
#define LSEQ    4096
#define DMODEL  1024
#define DINNER  2048
#define DCONV   4
#define DTRANK  64
#define DSTATE  16
#define DBLW    (DTRANK + 2*DSTATE)   // 96
#define CHUNK   128
#define NCHUNK  (LSEQ / CHUNK)        // 32
#define G2SPLIT 4

// ---------------- scratch (static device globals; zero-initialized) ----------------
__device__ float g_xr[(size_t)LSEQ * 2 * DINNER];          // [xi | res]
__device__ float g_xs[(size_t)LSEQ * DINNER];
__device__ float g_dblpart[(size_t)G2SPLIT * LSEQ * DBLW];
__device__ float g_dbl[(size_t)LSEQ * DBLW];
__device__ float g_delta[(size_t)LSEQ * DINNER];
__device__ float g_prodA[(size_t)NCHUNK * DINNER * DSTATE];
__device__ float g_hend [(size_t)NCHUNK * DINNER * DSTATE];
__device__ float g_hinit[(size_t)NCHUNK * DINNER * DSTATE];

// fp16 operands (128B-aligned for cp.async 16B)
__device__ __align__(128) __half g_xh  [(size_t)LSEQ * DMODEL];
__device__ __align__(128) __half g_winh[(size_t)2*DINNER * DMODEL];
__device__ __align__(128) __half g_wouth[(size_t)DMODEL * DINNER];
__device__ __align__(128) __half g_ygh [(size_t)LSEQ * DINNER];
__device__ __align__(128) __half g_xsh [(size_t)LSEQ * DINNER];
// W_x padded to 128 rows (rows 96..127 stay zero from static init)
__device__ __align__(128) __half g_wxh[(size_t)128 * DINNER];

// ================= low-level helpers (non-arch-specific PTX only) =================
__device__ __forceinline__ uint32_t smem_u32(const void* p) {
    uint32_t a;
    asm("{ .reg .u64 t; cvta.to.shared.u64 t, %1; cvt.u32.u64 %0, t; }" : "=r"(a) : "l"(p));
    return a;
}
__device__ __forceinline__ void cp16(uint32_t dst, const void* src) {
    asm volatile("cp.async.cg.shared.global [%0], [%1], 16;"
                 :: "r"(dst), "l"(__cvta_generic_to_global(src)));
}
#define CP_COMMIT() asm volatile("cp.async.commit_group;" ::: "memory")
#define CP_WAIT1()  asm volatile("cp.async.wait_group 1;" ::: "memory")

#define LDSM4(r, a) asm volatile( \
    "ldmatrix.sync.aligned.m8n8.x4.shared.b16 {%0,%1,%2,%3}, [%4];" \
    : "=r"((r)[0]), "=r"((r)[1]), "=r"((r)[2]), "=r"((r)[3]) : "r"(a))

#define MMA_F16(c, a, b) asm volatile( \
    "mma.sync.aligned.m16n8k16.row.col.f32.f16.f16.f32 " \
    "{%0,%1,%2,%3}, {%4,%5,%6,%7}, {%8,%9}, {%0,%1,%2,%3};" \
    : "+f"((c)[0]), "+f"((c)[1]), "+f"((c)[2]), "+f"((c)[3]) \
    : "r"((a)[0]), "r"((a)[1]), "r"((a)[2]), "r"((a)[3]), "r"((b)[0]), "r"((b)[1]))

// ================= fp16 GEMM (mma.sync) =================
// C[M,N](+split-K partials) = A[M,K] * B[N,K]^T, fp32 acc.
// CTA tile 128x128, BK=64 per stage, 8 warps (warp tile 32x64),
// 3-stage cp.async pipeline, ONE __syncthreads per stage.
// SMEM rows: 128B data + 16B pad = 144B stride; r*144 mod 128 = r*16 ->
// 8 consecutive rows hit 8 distinct 16B banks -> conflict-free ldmatrix.
#define ROWB     144
#define TILE_B   (128*ROWB)           // 18432
#define STAGE_B  (2*TILE_B)           // A,B = 36864
#define NSTAGE   3
#define GEMM_SMEM (NSTAGE*STAGE_B)    // 110592

__global__ __launch_bounds__(256, 2) void gemm_f16(
    const __half* __restrict__ A, const __half* __restrict__ B,
    float* __restrict__ C, int ldc, int Nvalid, int K,
    int kchunk, size_t splitStride)
{
    extern __shared__ __align__(128) char smem[];
    const uint32_t sbase = smem_u32(smem);
    const int tid  = threadIdx.x;
    const int wid  = tid >> 5;
    const int lane = tid & 31;
    const int rowBase = blockIdx.y * 128;
    const int colBase = blockIdx.x * 128;
    const int kbeg  = blockIdx.z * kchunk;
    const int niter = kchunk >> 6;         // BK=64
    C += (size_t)blockIdx.z * splitStride;

    const __half* srcA = A + (size_t)rowBase * K;
    const __half* srcB = B + (size_t)colBase * K;

    const int warp_row = wid & 3;   // 4 warps over M (32 rows each)
    const int warp_col = wid >> 2;  // 2 warps over N (64 cols each)
    const uint32_t aoff = (uint32_t)((warp_row*32 + (lane & 15)) * ROWB + (lane >> 4) * 16);
    const uint32_t boff = (uint32_t)((warp_col*64 + (lane >> 4)*8 + (lane & 7)) * ROWB
                                     + ((lane >> 3) & 1) * 16);

    float acc[2][8][4];
#pragma unroll
    for (int mt = 0; mt < 2; ++mt)
#pragma unroll
        for (int nt = 0; nt < 8; ++nt)
#pragma unroll
            for (int q = 0; q < 4; ++q) acc[mt][nt][q] = 0.f;

    auto load_stage = [&](int s) {
        const int kpos = kbeg + s * 64;
        const uint32_t db = sbase + (uint32_t)(s % NSTAGE) * STAGE_B;
#pragma unroll
        for (int q = 0; q < 4; ++q) {
            int i = tid + q * 256;        // 0..1023
            int r = i >> 3, c = i & 7;    // 128 rows x 8 16B-chunks
            cp16(db + (uint32_t)(r * ROWB + c * 16),          srcA + (size_t)r * K + kpos + c * 8);
            cp16(db + (uint32_t)(TILE_B + r * ROWB + c * 16), srcB + (size_t)r * K + kpos + c * 8);
        }
    };

    auto compute = [&](int s) {
        const uint32_t bb = sbase + (uint32_t)(s % NSTAGE) * STAGE_B;
#pragma unroll
        for (int kk = 0; kk < 4; ++kk) {   // 4 x k16
            uint32_t a[2][4], b[8][2];
#pragma unroll
            for (int mt = 0; mt < 2; ++mt)
                LDSM4(a[mt], bb + aoff + (uint32_t)(mt * 16*ROWB + kk * 32));  // 16 rows apart
#pragma unroll
            for (int p = 0; p < 4; ++p) {
                uint32_t r[4];
                LDSM4(r, bb + TILE_B + boff + (uint32_t)(p * 16*ROWB + kk * 32));
                b[2*p][0] = r[0]; b[2*p][1] = r[1]; b[2*p+1][0] = r[2]; b[2*p+1][1] = r[3];
            }
#pragma unroll
            for (int mt = 0; mt < 2; ++mt)
#pragma unroll
                for (int nt = 0; nt < 8; ++nt)
                    MMA_F16(acc[mt][nt], a[mt], b[nt]);
        }
    };

    load_stage(0); CP_COMMIT();
    load_stage(1); CP_COMMIT();

    for (int i = 0; i < niter; ++i) {
        CP_WAIT1();               // stage i resident (only i+1 may be in flight)
        __syncthreads();          // also guards slot reuse: all warps past compute(i-1)
        if (i + 2 < niter) load_stage(i + 2);
        CP_COMMIT();
        compute(i);
    }

    // epilogue: direct stores (8B per thread per fragment row)
#pragma unroll
    for (int mt = 0; mt < 2; ++mt) {
#pragma unroll
        for (int nt = 0; nt < 8; ++nt) {
            int m0 = rowBase + warp_row*32 + mt*16 + (lane >> 2);
            int n0 = colBase + warp_col*64 + nt*8 + (lane & 3)*2;
            if (n0 < Nvalid) {
                *(float2*)&C[(size_t)m0 * ldc + n0] =
                    make_float2(acc[mt][nt][0], acc[mt][nt][1]);
                *(float2*)&C[(size_t)(m0 + 8) * ldc + n0] =
                    make_float2(acc[mt][nt][2], acc[mt][nt][3]);
            }
        }
    }
}

// ---------------- fp32 -> fp16 convert ----------------
__global__ void cvt_f16(const float* __restrict__ in, __half* __restrict__ out, int n)
{
    int i = blockIdx.x * blockDim.x + threadIdx.x;
    if (i >= n) return;
    out[i] = __float2half(in[i]);
}

// ---------------- split-K partial reduce ----------------
__global__ void reduce_nz(const float* __restrict__ part, float* __restrict__ out,
                          int n, int nz)
{
    int i = blockIdx.x * blockDim.x + threadIdx.x;
    if (i >= n) return;
    float s = 0.f;
    for (int z = 0; z < nz; ++z) s += part[(size_t)z * n + i];
    out[i] = s;
}

// ---------------- fp32 SGEMM (kept for small G3) ----------------
#define GBM 128
#define GBN 128
#define GBK 8

__global__ __launch_bounds__(256) void sgemm_nt(
    const float* __restrict__ A, int lda,
    const float* __restrict__ B, int ldb,
    float* __restrict__ C, int ldc,
    int M, int N, int K,
    const float* __restrict__ bias, int act)
{
    __shared__ float As[GBK][GBM];
    __shared__ float Bs[GBK][GBN];

    const int tid = threadIdx.x;
    const int rowBase = blockIdx.y * GBM;
    const int colBase = blockIdx.x * GBN;

    const int lr = tid >> 1;
    const int lc = (tid & 1) * 4;

    const float* Aptr = A + (size_t)(rowBase + lr) * lda + lc;
    const float* Bptr = B + (size_t)(colBase + lr) * ldb + lc;
    const bool avalid = (rowBase + lr) < M;
    const bool bvalid = (colBase + lr) < N;

    const int tx = tid & 15;
    const int ty = tid >> 4;

    float acc[8][8];
#pragma unroll
    for (int i = 0; i < 8; ++i)
#pragma unroll
        for (int j = 0; j < 8; ++j) acc[i][j] = 0.f;

    for (int k0 = 0; k0 < K; k0 += GBK) {
        float4 av = avalid ? *(const float4*)(Aptr + k0) : make_float4(0.f,0.f,0.f,0.f);
        float4 bv = bvalid ? *(const float4*)(Bptr + k0) : make_float4(0.f,0.f,0.f,0.f);
        __syncthreads();
        As[lc+0][lr] = av.x; As[lc+1][lr] = av.y; As[lc+2][lr] = av.z; As[lc+3][lr] = av.w;
        Bs[lc+0][lr] = bv.x; Bs[lc+1][lr] = bv.y; Bs[lc+2][lr] = bv.z; Bs[lc+3][lr] = bv.w;
        __syncthreads();
#pragma unroll
        for (int kk = 0; kk < GBK; ++kk) {
            float4 a0 = *(const float4*)&As[kk][ty*4];
            float4 a1 = *(const float4*)&As[kk][64 + ty*4];
            float4 b0 = *(const float4*)&Bs[kk][tx*4];
            float4 b1 = *(const float4*)&Bs[kk][64 + tx*4];
            float ra[8] = {a0.x,a0.y,a0.z,a0.w,a1.x,a1.y,a1.z,a1.w};
            float rb[8] = {b0.x,b0.y,b0.z,b0.w,b1.x,b1.y,b1.z,b1.w};
#pragma unroll
            for (int i = 0; i < 8; ++i)
#pragma unroll
                for (int j = 0; j < 8; ++j)
                    acc[i][j] = fmaf(ra[i], rb[j], acc[i][j]);
        }
    }

#pragma unroll
    for (int i = 0; i < 8; ++i) {
        int row = rowBase + ((i < 4) ? (ty*4 + i) : (64 + ty*4 + i - 4));
        if (row >= M) continue;
#pragma unroll
        for (int j = 0; j < 8; ++j) {
            int col = colBase + ((j < 4) ? (tx*4 + j) : (64 + tx*4 + j - 4));
            if (col >= N) continue;
            float v = acc[i][j];
            if (bias) v += bias[col];
            if (act == 1) v = (v > 20.f) ? v : log1pf(__expf(v));  // softplus
            C[(size_t)row * ldc + col] = v;
        }
    }
}

// ---------------- causal depthwise conv(k=4) + bias + silu (+fp16 out) ----------------
__global__ void conv_silu(const float* __restrict__ xr,
                          const float* __restrict__ cw,
                          const float* __restrict__ cb,
                          float* __restrict__ xs,
                          __half* __restrict__ xsh)
{
    int idx = blockIdx.x * blockDim.x + threadIdx.x;
    if (idx >= LSEQ * DINNER) return;
    int t = idx / DINNER;
    int d = idx - t * DINNER;
    float acc = cb[d];
#pragma unroll
    for (int k = 0; k < DCONV; ++k) {
        int tt = t - (DCONV - 1) + k;
        if (tt >= 0) acc = fmaf(cw[d * DCONV + k], xr[(size_t)tt * (2*DINNER) + d], acc);
    }
    float sig = 1.f / (1.f + __expf(-acc));
    float v = acc * sig;
    xs[idx] = v;
    xsh[idx] = __float2half(v);
}

// ---------------- selective scan: 3-phase chunked ----------------
__global__ __launch_bounds__(256) void scan_phaseA(
    const float* __restrict__ delta, const float* __restrict__ xs,
    const float* __restrict__ dbl, const float* __restrict__ A_log,
    float* __restrict__ prodA, float* __restrict__ hend)
{
    const int tid = threadIdx.x;
    const int n  = tid & 15;
    const int d  = blockIdx.x * 16 + (tid >> 4);
    const int chunk = blockIdx.y;
    const float Adn = -__expf(A_log[d * DSTATE + n]);
    const float* Bp = dbl + DTRANK;

    float h = 0.f, pA = 1.f;
    const int t0 = chunk * CHUNK;
#pragma unroll 4
    for (int t = t0; t < t0 + CHUNK; ++t) {
        float dl = delta[(size_t)t * DINNER + d];
        float xv = xs[(size_t)t * DINNER + d];
        float b  = Bp[(size_t)t * DBLW + n];
        float a  = __expf(dl * Adn);
        h  = fmaf(a, h, dl * xv * b);
        pA *= a;
    }
    int idx = chunk * (DINNER * DSTATE) + d * DSTATE + n;
    prodA[idx] = pA;
    hend[idx]  = h;
}

__global__ void scan_phaseB(const float* __restrict__ prodA,
                            const float* __restrict__ hend,
                            float* __restrict__ hinit)
{
    int i = blockIdx.x * blockDim.x + threadIdx.x;
    if (i >= DINNER * DSTATE) return;
    float H = 0.f;
#pragma unroll
    for (int c = 0; c < NCHUNK; ++c) {
        int idx = c * (DINNER * DSTATE) + i;
        hinit[idx] = H;
        H = fmaf(prodA[idx], H, hend[idx]);
    }
}

__global__ __launch_bounds__(256) void scan_phaseC(
    const float* __restrict__ delta, const float* __restrict__ xs,
    const float* __restrict__ dbl, const float* __restrict__ A_log,
    const float* __restrict__ Dv, const float* __restrict__ xr,
    const float* __restrict__ hinit,
    __half* __restrict__ ygh)
{
    const int tid = threadIdx.x;
    const int n  = tid & 15;
    const int d  = blockIdx.x * 16 + (tid >> 4);
    const int chunk = blockIdx.y;
    const float Adn = -__expf(A_log[d * DSTATE + n]);
    const float Dd  = Dv[d];
    const float* Bp = dbl + DTRANK;
    const float* Cp = dbl + DTRANK + DSTATE;

    float h = hinit[chunk * (DINNER * DSTATE) + d * DSTATE + n];
    const int t0 = chunk * CHUNK;
#pragma unroll 2
    for (int t = t0; t < t0 + CHUNK; ++t) {
        float dl = delta[(size_t)t * DINNER + d];
        float xv = xs[(size_t)t * DINNER + d];
        float b  = Bp[(size_t)t * DBLW + n];
        float c  = Cp[(size_t)t * DBLW + n];
        float a  = __expf(dl * Adn);
        h = fmaf(a, h, dl * xv * b);
        float p = h * c;
        p += __shfl_xor_sync(0xffffffffu, p, 1, 16);
        p += __shfl_xor_sync(0xffffffffu, p, 2, 16);
        p += __shfl_xor_sync(0xffffffffu, p, 4, 16);
        p += __shfl_xor_sync(0xffffffffu, p, 8, 16);
        if (n == 0) {
            float r   = xr[(size_t)t * (2*DINNER) + DINNER + d];
            float sig = 1.f / (1.f + __expf(-r));
            float yv  = (p + xv * Dd) * (r * sig);
            ygh[(size_t)t * DINNER + d] = __float2half(yv);
        }
    }
}

// ---------------- launcher ----------------
extern "C" void kernel_launch(void* const* d_in, const int* in_sizes, int n_in,
                              void* d_out, int out_size)
{
    const float* x      = (const float*)d_in[0];
    const float* W_in   = (const float*)d_in[1];
    const float* conv_w = (const float*)d_in[2];
    const float* conv_b = (const float*)d_in[3];
    const float* W_x    = (const float*)d_in[4];
    const float* W_dt   = (const float*)d_in[5];
    const float* b_dt   = (const float*)d_in[6];
    const float* A_log  = (const float*)d_in[7];
    const float* Dv     = (const float*)d_in[8];
    const float* W_out  = (const float*)d_in[9];
    float* out = (float*)d_out;

    float *xr, *xs, *dblp, *dbl, *delta, *pA, *he, *hi;
    cudaGetSymbolAddress((void**)&xr,   g_xr);
    cudaGetSymbolAddress((void**)&xs,   g_xs);
    cudaGetSymbolAddress((void**)&dblp, g_dblpart);
    cudaGetSymbolAddress((void**)&dbl,  g_dbl);
    cudaGetSymbolAddress((void**)&delta,g_delta);
    cudaGetSymbolAddress((void**)&pA,   g_prodA);
    cudaGetSymbolAddress((void**)&he,   g_hend);
    cudaGetSymbolAddress((void**)&hi,   g_hinit);

    __half *xh, *winh, *wouth, *ygh, *xsh, *wxh;
    cudaGetSymbolAddress((void**)&xh,    g_xh);
    cudaGetSymbolAddress((void**)&winh,  g_winh);
    cudaGetSymbolAddress((void**)&wouth, g_wouth);
    cudaGetSymbolAddress((void**)&ygh,   g_ygh);
    cudaGetSymbolAddress((void**)&xsh,   g_xsh);
    cudaGetSymbolAddress((void**)&wxh,   g_wxh);

    cudaFuncSetAttribute(gemm_f16, cudaFuncAttributeMaxDynamicSharedMemorySize, GEMM_SMEM);

    // fp32 -> fp16 converts
    cvt_f16<<<(LSEQ*DMODEL + 255)/256, 256>>>(x, xh, LSEQ*DMODEL);
    cvt_f16<<<(2*DINNER*DMODEL + 255)/256, 256>>>(W_in, winh, 2*DINNER*DMODEL);
    cvt_f16<<<(DMODEL*DINNER + 255)/256, 256>>>(W_out, wouth, DMODEL*DINNER);
    cvt_f16<<<(DBLW*DINNER + 255)/256, 256>>>(W_x, wxh, DBLW*DINNER);  // rows 96..127 stay 0

    // G1 (mma): xr = x @ W_in^T -> 4096 x 4096
    gemm_f16<<<dim3(2*DINNER/128, LSEQ/128, 1), 256, GEMM_SMEM>>>(
        xh, winh, xr, 2*DINNER, 2*DINNER, DMODEL, DMODEL, 0);

    // conv + silu -> xs (fp32 + fp16)
    conv_silu<<<(LSEQ*DINNER + 255)/256, 256>>>(xr, conv_w, conv_b, xs, xsh);

    // G2 (mma, split-K x4): dbl = xs @ W_x^T (N=96, padded to 128)
    gemm_f16<<<dim3(1, LSEQ/128, G2SPLIT), 256, GEMM_SMEM>>>(
        xsh, wxh, dblp, DBLW, DBLW, DINNER, DINNER/G2SPLIT, (size_t)LSEQ*DBLW);
    reduce_nz<<<(LSEQ*DBLW + 255)/256, 256>>>(dblp, dbl, LSEQ*DBLW, G2SPLIT);

    // G3 (fp32): delta = softplus(dt_in @ W_dt^T + b_dt)
    sgemm_nt<<<dim3(DINNER/GBN, LSEQ/GBM, 1), 256>>>(
        dbl, DBLW, W_dt, DTRANK, delta, DINNER,
        LSEQ, DINNER, DTRANK, b_dt, 1);

    // selective scan (3 phases); phase C emits fp16 yg
    scan_phaseA<<<dim3(DINNER/16, NCHUNK), 256>>>(delta, xs, dbl, A_log, pA, he);
    scan_phaseB<<<(DINNER*DSTATE + 255)/256, 256>>>(pA, he, hi);
    scan_phaseC<<<dim3(DINNER/16, NCHUNK), 256>>>(delta, xs, dbl, A_log, Dv, xr, hi, ygh);

    // G4 (mma): out = yg @ W_out^T -> 4096 x 1024
    gemm_f16<<<dim3(DMODEL/128, LSEQ/128, 1), 256, GEMM_SMEM>>>(
        ygh, wouth, out, DMODEL, DMODEL, DINNER, DINNER, 0);
}